// round 15
// baseline (speedup 1.0000x reference)
#include <cuda_runtime.h>
#include <cstdint>

#define Bb 16
#define Nn 16
#define Hh 512
#define Ww 512
#define HW (Hh * Ww)
#define HW4 (HW / 4)          // 65536 float4 per (b,n) slice
#define THREADS 256
#define SPLIT 4
#define CHUNK8 (HW / 8 / SPLIT)   // 8192 32-byte units per block
#define UB 2
#define OUTER (CHUNK8 / (THREADS * UB))   // 16
#define GRID (Bb * Nn * SPLIT)            // 1024

__device__ float    g_ov[Bb * Nn];
__device__ float    g_it[Bb * Nn];
__device__ float    g_ts[Bb * Nn];
__device__ unsigned g_done;

// 256-bit loads (sm_100+). Non-volatile: ptxas may schedule freely.
__device__ __forceinline__ void ld256_cs(const float* p, float* f) {
    asm("ld.global.cs.v8.f32 {%0,%1,%2,%3,%4,%5,%6,%7}, [%8];"
        : "=f"(f[0]), "=f"(f[1]), "=f"(f[2]), "=f"(f[3]),
          "=f"(f[4]), "=f"(f[5]), "=f"(f[6]), "=f"(f[7])
        : "l"(p));
}
__device__ __forceinline__ void ld256_ca(const float* p, float* f) {
    asm("ld.global.ca.v8.f32 {%0,%1,%2,%3,%4,%5,%6,%7}, [%8];"
        : "=f"(f[0]), "=f"(f[1]), "=f"(f[2]), "=f"(f[3]),
          "=f"(f[4]), "=f"(f[5]), "=f"(f[6]), "=f"(f[7])
        : "l"(p));
}

__global__ __launch_bounds__(THREADS)
void stream_kernel(const float* __restrict__ masks,
                   const float* __restrict__ target,
                   const int*   __restrict__ boxes,
                   float*       __restrict__ out)
{
    const int blk   = blockIdx.x;          // 0..1023
    const int bn    = blk / SPLIT;         // 0..255
    const int split = blk % SPLIT;
    const int b     = bn >> 4;

    const int tid = threadIdx.x;

    // byte base of this block's chunk within the slice (in floats)
    const size_t chunk_f = (size_t)split * CHUNK8 * 8;     // floats
    const float* __restrict__ mp = masks  + (size_t)bn * HW + chunk_f + (size_t)tid * 8;
    const float* __restrict__ tp = target + (size_t)b  * HW + chunk_f + (size_t)tid * 8;

    const int4 box = reinterpret_cast<const int4*>(boxes)[bn];
    const int x1 = box.x, y1 = box.y, x2 = box.z, y2 = box.w;

    // k-invariant column selectors: this thread covers cols w0..w0+7
    const int w0 = (tid & 63) << 3;        // 64 units of 8 floats per 512-col row
    float c[8];
    #pragma unroll
    for (int e = 0; e < 8; e++)
        c[e] = (w0 + e >= x1 && w0 + e < x2) ? 1.f : 0.f;

    // row for k-step 0; each 256-unit step advances 4 rows
    int h = split * (CHUNK8 / 64) + (tid >> 6);

    float ov = 0.f, ts = 0.f, it = 0.f;

    for (int kk = 0; kk < OUTER; kk++) {
        float mv[UB][8], tv[UB][8];
        #pragma unroll
        for (int u = 0; u < UB; u++) {
            ld256_cs(mp + (size_t)u * THREADS * 8, mv[u]);  // masks: evict-first
            ld256_ca(tp + (size_t)u * THREADS * 8, tv[u]);  // target: cached
        }
        mp += (size_t)UB * THREADS * 8;
        tp += (size_t)UB * THREADS * 8;

        #pragma unroll
        for (int u = 0; u < UB; u++) {
            #pragma unroll
            for (int e = 0; e < 8; e++)
                ov = fmaf(mv[u][e], tv[u][e], ov);

            float rs = 0.f;
            #pragma unroll
            for (int e = 0; e < 8; e++) rs += tv[u][e];
            ts += rs;

            const int hu = h + 4 * u;
            if (hu >= y1 && hu < y2) {       // warp-uniform branch
                float s = 0.f;
                #pragma unroll
                for (int e = 0; e < 8; e++)
                    s = fmaf(c[e], tv[u][e], s);
                it += s;
            }
        }
        h += 4 * UB;
    }

    // ---- single block reduction ----
    const unsigned FULL = 0xFFFFFFFFu;
    #pragma unroll
    for (int off = 16; off > 0; off >>= 1) {
        ov += __shfl_xor_sync(FULL, ov, off);
        ts += __shfl_xor_sync(FULL, ts, off);
        it += __shfl_xor_sync(FULL, it, off);
    }

    __shared__ float s_ov[THREADS / 32];
    __shared__ float s_ts[THREADS / 32];
    __shared__ float s_it[THREADS / 32];
    const int wid = tid >> 5;
    const int lid = tid & 31;
    if (lid == 0) { s_ov[wid] = ov; s_ts[wid] = ts; s_it[wid] = it; }
    __syncthreads();

    if (tid < 3) {
        float sum = 0.f;
        if (tid == 0) {
            #pragma unroll
            for (int w = 0; w < THREADS / 32; w++) sum += s_ov[w];
            atomicAdd(&g_ov[bn], sum);
        } else if (tid == 1) {
            #pragma unroll
            for (int w = 0; w < THREADS / 32; w++) sum += s_it[w];
            atomicAdd(&g_it[bn], sum);
        } else {
            #pragma unroll
            for (int w = 0; w < THREADS / 32; w++) sum += s_ts[w];
            atomicAdd(&g_ts[bn], sum);
        }
    }
    __threadfence();
    __syncthreads();

    __shared__ unsigned s_last;
    if (tid == 0) s_last = atomicAdd(&g_done, 1u);
    __syncthreads();

    // ---- last block finalizes + resets (graph-replay safe) ----
    if (s_last == GRID - 1) {
        const int j = tid;                     // 0..255 = one per bn
        const float ovv = *(volatile float*)&g_ov[j];
        const float itv = *(volatile float*)&g_it[j];
        const float tsv = *(volatile float*)&g_ts[j];
        const int4 bx = reinterpret_cast<const int4*>(boxes)[j];
        const float area = (float)(bx.z - bx.x) * (float)(bx.w - bx.y);
        const float uni = area + tsv - itv;
        out[j * 2 + 0] = ovv;
        out[j * 2 + 1] = itv / (uni + 1e-8f);
        g_ov[j] = 0.f;
        g_it[j] = 0.f;
        g_ts[j] = 0.f;
        if (j == 0) g_done = 0u;
    }
}

extern "C" void kernel_launch(void* const* d_in, const int* in_sizes, int n_in,
                              void* d_out, int out_size)
{
    const float* masks  = (const float*)d_in[0];   // (B,N,H,W) f32
    const float* target = (const float*)d_in[1];   // (B,H,W)   f32
    const int*   boxes  = (const int*)d_in[2];     // (B,N,4)   i32
    float* out = (float*)d_out;                    // (B,N,2)   f32

    stream_kernel<<<GRID, THREADS>>>(masks, target, boxes, out);
}

// round 16
// speedup vs baseline: 1.2217x; 1.2217x over previous
#include <cuda_runtime.h>
#include <cstdint>

#define Bb 16
#define Nn 16
#define Hh 512
#define Ww 512
#define HW (Hh * Ww)
#define HW4 (HW / 4)        // 65536 float4 per (b,n) slice
#define W4 (Ww / 4)         // 128 float4 per row
#define THREADS 256
#define SPLIT 4
#define CHUNK (HW4 / SPLIT) // 16384 float4 per block
#define UB 8                // load batch
#define OUTER (CHUNK / (THREADS * UB))  // 8
#define GRID (Bb * Nn * SPLIT)          // 1024

__device__ float    g_ov[Bb * Nn];
__device__ float    g_it[Bb * Nn];
__device__ float    g_ts[Bb * Nn];
__device__ unsigned g_done;

__global__ __launch_bounds__(THREADS)
void stream_kernel(const float* __restrict__ masks,
                   const float* __restrict__ target,
                   const int*   __restrict__ boxes,
                   float*       __restrict__ out)
{
    const int blk   = blockIdx.x;          // 0..1023
    const int bn    = blk / SPLIT;         // 0..255
    const int split = blk % SPLIT;
    const int b     = bn >> 4;

    const int tid = threadIdx.x;
    const int base = split * CHUNK;

    const float4* __restrict__ mp = (const float4*)masks + (size_t)bn * HW4 + base + tid;
    const float4* __restrict__ tp = (const float4*)target + (size_t)b  * HW4 + base + tid;

    const int4 box = reinterpret_cast<const int4*>(boxes)[bn];
    const int x1 = box.x, y1 = box.y, x2 = box.z, y2 = box.w;

    // k-invariant column selectors for this thread's float4 lane
    const int w0 = (tid & (W4 - 1)) << 2;
    const float c0 = (w0     >= x1 && w0     < x2) ? 1.f : 0.f;
    const float c1 = (w0 + 1 >= x1 && w0 + 1 < x2) ? 1.f : 0.f;
    const float c2 = (w0 + 2 >= x1 && w0 + 2 < x2) ? 1.f : 0.f;
    const float c3 = (w0 + 3 >= x1 && w0 + 3 < x2) ? 1.f : 0.f;

    // row index: advances by 2 per k-step (stride 256 float4 = 2 rows)
    int h = (base >> 7) + (tid >> 7);

    float ov = 0.f, ts = 0.f, it = 0.f;

    for (int kk = 0; kk < OUTER; kk++) {
        float4 mv[UB], tv[UB];
        // DRAM-missing mask loads first, L2-hitting target loads in their shadow
        #pragma unroll
        for (int u = 0; u < UB; u++)
            mv[u] = __ldcs(mp + u * THREADS);   // streaming, evict-first
        #pragma unroll
        for (int u = 0; u < UB; u++)
            tv[u] = __ldg(tp + u * THREADS);    // L2-resident, reused by 16 bn
        mp += UB * THREADS;
        tp += UB * THREADS;

        #pragma unroll
        for (int u = 0; u < UB; u++) {
            ov = fmaf(mv[u].x, tv[u].x, ov);
            ov = fmaf(mv[u].y, tv[u].y, ov);
            ov = fmaf(mv[u].z, tv[u].z, ov);
            ov = fmaf(mv[u].w, tv[u].w, ov);

            ts += (tv[u].x + tv[u].y) + (tv[u].z + tv[u].w);

            const int hu = h + 2 * u;
            if (hu >= y1 && hu < y2) {
                float s;
                s = fmaf(c0, tv[u].x, 0.f);
                s = fmaf(c1, tv[u].y, s);
                s = fmaf(c2, tv[u].z, s);
                s = fmaf(c3, tv[u].w, s);
                it += s;
            }
        }
        h += 2 * UB;
    }

    // ---- single block reduction ----
    const unsigned FULL = 0xFFFFFFFFu;
    #pragma unroll
    for (int off = 16; off > 0; off >>= 1) {
        ov += __shfl_xor_sync(FULL, ov, off);
        ts += __shfl_xor_sync(FULL, ts, off);
        it += __shfl_xor_sync(FULL, it, off);
    }

    __shared__ float s_ov[THREADS / 32];
    __shared__ float s_ts[THREADS / 32];
    __shared__ float s_it[THREADS / 32];
    const int wid = tid >> 5;
    const int lid = tid & 31;
    if (lid == 0) { s_ov[wid] = ov; s_ts[wid] = ts; s_it[wid] = it; }
    __syncthreads();

    if (tid < 3) {
        float sum = 0.f;
        if (tid == 0) {
            #pragma unroll
            for (int w = 0; w < THREADS / 32; w++) sum += s_ov[w];
            atomicAdd(&g_ov[bn], sum);
        } else if (tid == 1) {
            #pragma unroll
            for (int w = 0; w < THREADS / 32; w++) sum += s_it[w];
            atomicAdd(&g_it[bn], sum);
        } else {
            #pragma unroll
            for (int w = 0; w < THREADS / 32; w++) sum += s_ts[w];
            atomicAdd(&g_ts[bn], sum);
        }
    }
    __threadfence();
    __syncthreads();

    __shared__ unsigned s_last;
    if (tid == 0) s_last = atomicAdd(&g_done, 1u);
    __syncthreads();

    // ---- last block finalizes + resets (graph-replay safe) ----
    if (s_last == GRID - 1) {
        const int j = tid;                     // 0..255 = one per bn
        const float ovv = *(volatile float*)&g_ov[j];
        const float itv = *(volatile float*)&g_it[j];
        const float tsv = *(volatile float*)&g_ts[j];
        const int4 bx = reinterpret_cast<const int4*>(boxes)[j];
        const float area = (float)(bx.z - bx.x) * (float)(bx.w - bx.y);
        const float uni = area + tsv - itv;
        out[j * 2 + 0] = ovv;
        out[j * 2 + 1] = itv / (uni + 1e-8f);
        g_ov[j] = 0.f;
        g_it[j] = 0.f;
        g_ts[j] = 0.f;
        if (j == 0) g_done = 0u;
    }
}

extern "C" void kernel_launch(void* const* d_in, const int* in_sizes, int n_in,
                              void* d_out, int out_size)
{
    const float* masks  = (const float*)d_in[0];   // (B,N,H,W) f32
    const float* target = (const float*)d_in[1];   // (B,H,W)   f32
    const int*   boxes  = (const int*)d_in[2];     // (B,N,4)   i32
    float* out = (float*)d_out;                    // (B,N,2)   f32

    stream_kernel<<<GRID, THREADS>>>(masks, target, boxes, out);
}